// round 12
// baseline (speedup 1.0000x reference)
#include <cuda_runtime.h>
#include <cuda_bf16.h>

// USER_NUM=1000, SKILL_NUM=256, K_HIDDEN=128, N_ITEMS=4096, SEQ_LEN=8192
// out[l, k] = sum_{s : Q[items[l], s] != 0} E[user, s, k]
//
// SINGLE persistent kernel (one launch -> one launch floor):
//   Phase A: split-K per-item partial row-sums into g_partial[item*2+half]
//   device-wide barrier (monotonic counter, replay-safe, <=148 CTAs so all
//   CTAs are co-resident -> no deadlock)
//   Phase B: out[l] = P[items[l]*2] + P[items[l]*2+1], grid-stride, coalesced

#define SEQ_LEN   8192
#define N_ITEMS   4096
#define SKILLS    256
#define K_HIDDEN  128
#define NNZ_CAP   64          // binomial(128,0.1): mean 12.8, std 3.4
#define GRID_CTAS 148
#define CTA_THREADS 256
#define CTA_WARPS  (CTA_THREADS / 32)

// Partial sums: 8192 x 32 float4 = 4 MB static device scratch (no alloc)
__device__ float4   g_partial[2 * N_ITEMS * (K_HIDDEN / 4)];
// Monotonic barrier counter: zero-initialized at module load; never reset.
__device__ unsigned g_arrive;

__global__ void __launch_bounds__(CTA_THREADS)
fused_persistent(const int* __restrict__ user_p,
                 const float* __restrict__ Q,     // [N_ITEMS, SKILLS]
                 const int* __restrict__ items,   // [SEQ_LEN]
                 const float* __restrict__ emb,   // [USER_NUM, SKILLS, K_HIDDEN]
                 float4* __restrict__ out4)       // [SEQ_LEN * 32]
{
    __shared__ int      sidx[CTA_WARPS][NNZ_CAP];
    __shared__ unsigned s_target;

    const int tid  = threadIdx.x;
    const int w    = tid >> 5;
    const int lane = tid & 31;
    const int gwarp   = blockIdx.x * CTA_WARPS + w;
    const int nwarps  = GRID_CTAS * CTA_WARPS;          // 1184

    const int user = user_p[0];
    const float4* __restrict__ E4 =
        reinterpret_cast<const float4*>(emb + (long long)user * SKILLS * K_HIDDEN) + lane;

    // ================= Phase A: item-half partial row-sums =================
    const unsigned lt_mask = (1u << lane) - 1u;
    for (int task = gwarp; task < 2 * N_ITEMS; task += nwarps) {
        const int item = task >> 1;
        const int half = task & 1;

        // This half's 128 skills: one coalesced float4 per lane
        const float4 v = reinterpret_cast<const float4*>(
            Q + (long long)item * SKILLS + half * 128)[lane];

        // Ballot-compact nonzero skill ids
        const int s_base = half * 128 + 4 * lane;
        const float vals[4] = {v.x, v.y, v.z, v.w};
        int nnz = 0;
        #pragma unroll
        for (int t = 0; t < 4; t++) {
            const bool nz = (vals[t] != 0.0f);
            const unsigned m = __ballot_sync(0xffffffffu, nz);
            if (nz) {
                const int p = nnz + __popc(m & lt_mask);
                if (p < NNZ_CAP) sidx[w][p] = s_base + t;
            }
            nnz += __popc(m);
        }
        __syncwarp();
        nnz = min(nnz, NNZ_CAP);

        // Gather-accumulate: batch of 8 in flight; typical nnz ~13
        float4 a0 = make_float4(0.f, 0.f, 0.f, 0.f);
        float4 a1 = make_float4(0.f, 0.f, 0.f, 0.f);
        int j = 0;
        for (; j + 8 <= nnz; j += 8) {
            int s[8];
            #pragma unroll
            for (int t = 0; t < 8; t++) s[t] = sidx[w][j + t];
            float4 e[8];
            #pragma unroll
            for (int t = 0; t < 8; t++) e[t] = E4[s[t] * 32];
            #pragma unroll
            for (int t = 0; t < 4; t++) {
                a0.x += e[t].x;   a0.y += e[t].y;   a0.z += e[t].z;   a0.w += e[t].w;
                a1.x += e[t+4].x; a1.y += e[t+4].y; a1.z += e[t+4].z; a1.w += e[t+4].w;
            }
        }
        if (j + 4 <= nnz) {
            const int s0 = sidx[w][j+0], s1 = sidx[w][j+1];
            const int s2 = sidx[w][j+2], s3 = sidx[w][j+3];
            const float4 e0 = E4[s0 * 32];
            const float4 e1 = E4[s1 * 32];
            const float4 e2 = E4[s2 * 32];
            const float4 e3 = E4[s3 * 32];
            a0.x += (e0.x + e1.x) + (e2.x + e3.x);
            a0.y += (e0.y + e1.y) + (e2.y + e3.y);
            a0.z += (e0.z + e1.z) + (e2.z + e3.z);
            a0.w += (e0.w + e1.w) + (e2.w + e3.w);
            j += 4;
        }
        for (; j < nnz; j++) {
            const float4 e = E4[sidx[w][j] * 32];
            a1.x += e.x; a1.y += e.y; a1.z += e.z; a1.w += e.w;
        }

        float4 acc;
        acc.x = a0.x + a1.x; acc.y = a0.y + a1.y;
        acc.z = a0.z + a1.z; acc.w = a0.w + a1.w;
        g_partial[task * 32 + lane] = acc;   // interleaved: halves of an item adjacent
        __syncwarp();                        // protect sidx reuse next iteration
    }

    // ================= Device-wide barrier (replay-safe, no reset) =========
    __syncthreads();
    if (tid == 0) {
        __threadfence();                                  // release phase-A writes
        const unsigned ticket = atomicAdd(&g_arrive, 1u);
        // This replay's batch ends at (ticket - ticket%G) + G
        s_target = ticket - (ticket % GRID_CTAS) + GRID_CTAS;
    }
    __syncthreads();
    if (tid == 0) {
        const unsigned target = s_target;
        unsigned v;
        do {
            asm volatile("ld.acquire.gpu.u32 %0, [%1];"
                         : "=r"(v) : "l"(&g_arrive) : "memory");
        } while ((int)(v - target) < 0);                  // wrap-safe compare
    }
    __syncthreads();                                      // all threads see acquire

    // ================= Phase B: out[l] = P[2*it] + P[2*it+1] ===============
    const int tidg     = blockIdx.x * CTA_THREADS + tid;
    const int nthreads = GRID_CTAS * CTA_THREADS;         // 37888
    const int total    = SEQ_LEN * (K_HIDDEN / 4);        // 262144
    for (int g = tidg; g < total; g += nthreads) {
        const int pos = g >> 5;
        const int q   = g & 31;
        const int it  = __ldg(&items[pos]);
        const float4 r0 = g_partial[(it * 2)     * 32 + q];
        const float4 r1 = g_partial[(it * 2 + 1) * 32 + q];
        float4 o;
        o.x = r0.x + r1.x; o.y = r0.y + r1.y;
        o.z = r0.z + r1.z; o.w = r0.w + r1.w;
        out4[g] = o;
    }
}

extern "C" void kernel_launch(void* const* d_in, const int* in_sizes, int n_in,
                              void* d_out, int out_size)
{
    const int*   user  = nullptr;
    const float* Q     = nullptr;
    const int*   items = nullptr;
    const float* emb   = nullptr;

    for (int i = 0; i < n_in; i++) {
        switch (in_sizes[i]) {
            case 1:                        user  = (const int*)  d_in[i]; break;
            case N_ITEMS * SKILLS:         Q     = (const float*)d_in[i]; break;
            case SEQ_LEN:                  items = (const int*)  d_in[i]; break;
            case 1000 * SKILLS * K_HIDDEN: emb   = (const float*)d_in[i]; break;
            default: break;
        }
    }
    if (!user)  user  = (const int*)  d_in[0];
    if (!Q)     Q     = (const float*)d_in[1];
    if (!items) items = (const int*)  d_in[2];
    if (!emb)   emb   = (const float*)d_in[3];

    // ONE launch; grid <= SM count so all CTAs are co-resident (barrier-safe)
    fused_persistent<<<GRID_CTAS, CTA_THREADS>>>(user, Q, items, emb, (float4*)d_out);
}

// round 13
// speedup vs baseline: 1.3208x; 1.3208x over previous
#include <cuda_runtime.h>
#include <cuda_bf16.h>

// USER_NUM=1000, SKILL_NUM=256, K_HIDDEN=128, N_ITEMS=4096, SEQ_LEN=8192
// out[l, k] = sum_{s : Q[items[l], s] != 0} E[user, s, k]
//
// SINGLE persistent kernel, HIGH occupancy (R12 lesson: 148 CTAs = 8 warps/SM
// killed latency hiding; launch overhead is only ~2.3us/kernel):
//   grid = 888 CTAs (6 CTAs/SM x 148, provably co-resident at 1536 thr/SM)
//   Phase A: split-K per-item partial row-sums into g_partial[item*2+half]
//   device-wide barrier (monotonic counter, replay-safe, no reset)
//   Phase B: out[l] = P[2*it] + P[2*it+1], grid-stride, coalesced

#define SEQ_LEN   8192
#define N_ITEMS   4096
#define SKILLS    256
#define K_HIDDEN  128
#define NNZ_CAP   64          // binomial(128,0.1): mean 12.8, std 3.4
#define CTAS_PER_SM 6
#define NUM_SMS   148
#define GRID_CTAS (NUM_SMS * CTAS_PER_SM)     // 888
#define CTA_THREADS 256
#define CTA_WARPS  (CTA_THREADS / 32)

// Partial sums: 8192 x 32 float4 = 4 MB static device scratch (no alloc)
__device__ float4   g_partial[2 * N_ITEMS * (K_HIDDEN / 4)];
// Monotonic barrier counter: zero-initialized at module load; never reset.
__device__ unsigned g_arrive;

__global__ void __launch_bounds__(CTA_THREADS, CTAS_PER_SM)
fused_persistent_hiocc(const int* __restrict__ user_p,
                       const float* __restrict__ Q,     // [N_ITEMS, SKILLS]
                       const int* __restrict__ items,   // [SEQ_LEN]
                       const float* __restrict__ emb,   // [USER_NUM, SKILLS, K_HIDDEN]
                       float4* __restrict__ out4)       // [SEQ_LEN * 32]
{
    __shared__ int      sidx[CTA_WARPS][NNZ_CAP];
    __shared__ unsigned s_target;

    const int tid  = threadIdx.x;
    const int w    = tid >> 5;
    const int lane = tid & 31;
    const int gwarp  = blockIdx.x * CTA_WARPS + w;
    const int nwarps = GRID_CTAS * CTA_WARPS;           // 7104

    const int user = user_p[0];
    const float4* __restrict__ E4 =
        reinterpret_cast<const float4*>(emb + (long long)user * SKILLS * K_HIDDEN) + lane;

    // ================= Phase A: item-half partial row-sums =================
    const unsigned lt_mask = (1u << lane) - 1u;
    for (int task = gwarp; task < 2 * N_ITEMS; task += nwarps) {
        const int item = task >> 1;
        const int half = task & 1;

        // This half's 128 skills: one coalesced float4 per lane
        const float4 v = reinterpret_cast<const float4*>(
            Q + (long long)item * SKILLS + half * 128)[lane];

        // Ballot-compact nonzero skill ids
        const int s_base = half * 128 + 4 * lane;
        const float vals[4] = {v.x, v.y, v.z, v.w};
        int nnz = 0;
        #pragma unroll
        for (int t = 0; t < 4; t++) {
            const bool nz = (vals[t] != 0.0f);
            const unsigned m = __ballot_sync(0xffffffffu, nz);
            if (nz) {
                const int p = nnz + __popc(m & lt_mask);
                if (p < NNZ_CAP) sidx[w][p] = s_base + t;
            }
            nnz += __popc(m);
        }
        __syncwarp();
        nnz = min(nnz, NNZ_CAP);

        // Gather-accumulate: batch of 8 in flight; typical nnz ~13
        float4 a0 = make_float4(0.f, 0.f, 0.f, 0.f);
        float4 a1 = make_float4(0.f, 0.f, 0.f, 0.f);
        int j = 0;
        for (; j + 8 <= nnz; j += 8) {
            int s[8];
            #pragma unroll
            for (int t = 0; t < 8; t++) s[t] = sidx[w][j + t];
            float4 e[8];
            #pragma unroll
            for (int t = 0; t < 8; t++) e[t] = E4[s[t] * 32];
            #pragma unroll
            for (int t = 0; t < 4; t++) {
                a0.x += e[t].x;   a0.y += e[t].y;   a0.z += e[t].z;   a0.w += e[t].w;
                a1.x += e[t+4].x; a1.y += e[t+4].y; a1.z += e[t+4].z; a1.w += e[t+4].w;
            }
        }
        if (j + 4 <= nnz) {
            const int s0 = sidx[w][j+0], s1 = sidx[w][j+1];
            const int s2 = sidx[w][j+2], s3 = sidx[w][j+3];
            const float4 e0 = E4[s0 * 32];
            const float4 e1 = E4[s1 * 32];
            const float4 e2 = E4[s2 * 32];
            const float4 e3 = E4[s3 * 32];
            a0.x += (e0.x + e1.x) + (e2.x + e3.x);
            a0.y += (e0.y + e1.y) + (e2.y + e3.y);
            a0.z += (e0.z + e1.z) + (e2.z + e3.z);
            a0.w += (e0.w + e1.w) + (e2.w + e3.w);
            j += 4;
        }
        for (; j < nnz; j++) {
            const float4 e = E4[sidx[w][j] * 32];
            a1.x += e.x; a1.y += e.y; a1.z += e.z; a1.w += e.w;
        }

        float4 acc;
        acc.x = a0.x + a1.x; acc.y = a0.y + a1.y;
        acc.z = a0.z + a1.z; acc.w = a0.w + a1.w;
        g_partial[task * 32 + lane] = acc;   // halves of an item adjacent (512B apart)
        __syncwarp();                        // protect sidx reuse next iteration
    }

    // ================= Device-wide barrier (replay-safe, no reset) =========
    __syncthreads();
    if (tid == 0) {
        __threadfence();                                  // release phase-A writes
        const unsigned ticket = atomicAdd(&g_arrive, 1u);
        // This replay's batch ends at (ticket - ticket%G) + G
        s_target = ticket - (ticket % GRID_CTAS) + GRID_CTAS;
    }
    __syncthreads();
    if (tid == 0) {
        const unsigned target = s_target;
        unsigned v;
        do {
            asm volatile("ld.acquire.gpu.u32 %0, [%1];"
                         : "=r"(v) : "l"(&g_arrive) : "memory");
        } while ((int)(v - target) < 0);                  // wrap-safe compare
    }
    __syncthreads();                                      // all threads see acquire

    // ================= Phase B: out[l] = P[2*it] + P[2*it+1] ===============
    const int tidg     = blockIdx.x * CTA_THREADS + tid;
    const int nthreads = GRID_CTAS * CTA_THREADS;         // 227328
    const int total    = SEQ_LEN * (K_HIDDEN / 4);        // 262144
    for (int g = tidg; g < total; g += nthreads) {
        const int pos = g >> 5;
        const int q   = g & 31;
        const int it  = __ldg(&items[pos]);
        const float4 r0 = g_partial[(it * 2)     * 32 + q];
        const float4 r1 = g_partial[(it * 2 + 1) * 32 + q];
        float4 o;
        o.x = r0.x + r1.x; o.y = r0.y + r1.y;
        o.z = r0.z + r1.z; o.w = r0.w + r1.w;
        out4[g] = o;
    }
}

extern "C" void kernel_launch(void* const* d_in, const int* in_sizes, int n_in,
                              void* d_out, int out_size)
{
    const int*   user  = nullptr;
    const float* Q     = nullptr;
    const int*   items = nullptr;
    const float* emb   = nullptr;

    for (int i = 0; i < n_in; i++) {
        switch (in_sizes[i]) {
            case 1:                        user  = (const int*)  d_in[i]; break;
            case N_ITEMS * SKILLS:         Q     = (const float*)d_in[i]; break;
            case SEQ_LEN:                  items = (const int*)  d_in[i]; break;
            case 1000 * SKILLS * K_HIDDEN: emb   = (const float*)d_in[i]; break;
            default: break;
        }
    }
    if (!user)  user  = (const int*)  d_in[0];
    if (!Q)     Q     = (const float*)d_in[1];
    if (!items) items = (const int*)  d_in[2];
    if (!emb)   emb   = (const float*)d_in[3];

    // ONE launch; 6 CTAs/SM x 148 SMs, co-resident by occupancy bound
    fused_persistent_hiocc<<<GRID_CTAS, CTA_THREADS>>>(user, Q, items, emb, (float4*)d_out);
}